// round 2
// baseline (speedup 1.0000x reference)
#include <cuda_runtime.h>
#include <cuda_bf16.h>
#include <cstdint>

#define B_ROWS 8192
#define DFEAT  512
#define KOUT   1024

// Scratch (allowed: __device__ globals, no dynamic allocation)
__device__ __nv_bfloat16 g_xb[B_ROWS * DFEAT];   // 8 MB
__device__ __nv_bfloat16 g_wb[KOUT * DFEAT];     // 1 MB
__device__ float g_xsq[B_ROWS];
__device__ float g_wsq[KOUT];

// ---------------------------------------------------------------------------
// Kernel 1: convert x,w to bf16 and compute row squared norms.
// One warp per row (512 floats = 16 per lane).
// ---------------------------------------------------------------------------
__global__ void prep_kernel(const float* __restrict__ x, const float* __restrict__ w) {
    int gwarp = (blockIdx.x * blockDim.x + threadIdx.x) >> 5;
    int lane  = threadIdx.x & 31;

    const float* src;
    __nv_bfloat16* dst;
    float* sqdst;
    int sqidx;
    if (gwarp < B_ROWS) {
        src = x + (size_t)gwarp * DFEAT;
        dst = g_xb + (size_t)gwarp * DFEAT;
        sqdst = g_xsq; sqidx = gwarp;
    } else if (gwarp < B_ROWS + KOUT) {
        int r = gwarp - B_ROWS;
        src = w + (size_t)r * DFEAT;
        dst = g_wb + (size_t)r * DFEAT;
        sqdst = g_wsq; sqidx = r;
    } else {
        return;
    }

    float s = 0.0f;
#pragma unroll
    for (int i = 0; i < 4; i++) {
        int col = i * 128 + lane * 4;
        float4 v = *reinterpret_cast<const float4*>(src + col);
        s += v.x * v.x + v.y * v.y + v.z * v.z + v.w * v.w;
        __nv_bfloat162 p0 = __float22bfloat162_rn(make_float2(v.x, v.y));
        __nv_bfloat162 p1 = __float22bfloat162_rn(make_float2(v.z, v.w));
        __nv_bfloat162* d2 = reinterpret_cast<__nv_bfloat162*>(dst + col);
        d2[0] = p0;
        d2[1] = p1;
    }
#pragma unroll
    for (int off = 16; off >= 1; off >>= 1)
        s += __shfl_xor_sync(0xFFFFFFFFu, s, off);
    if (lane == 0) sqdst[sqidx] = s;
}

// ---------------------------------------------------------------------------
// Kernel 2: bf16 tensor-core GEMM (mma.sync m16n8k16) with fused epilogue
//   q_un = 1/(1 + max(xsq + wsq - 2*acc, 0))
// CTA tile 128(M) x 128(N), K-chunks of 64. 8 warps = 4(M) x 2(N),
// warp tile 32x64 = 2x8 mma tiles, 64 fp32 accum regs/thread.
// ---------------------------------------------------------------------------
#define SA_STRIDE 72   // 64 + 8 bf16 padding; row pitch 144B (16B aligned, conflict-free)

__device__ __forceinline__ void ldmatrix_x4(uint32_t& r0, uint32_t& r1,
                                            uint32_t& r2, uint32_t& r3,
                                            uint32_t saddr) {
    asm volatile("ldmatrix.sync.aligned.m8n8.x4.shared.b16 {%0,%1,%2,%3}, [%4];"
                 : "=r"(r0), "=r"(r1), "=r"(r2), "=r"(r3) : "r"(saddr));
}

__device__ __forceinline__ void mma_bf16(float* d, const uint32_t* a,
                                         uint32_t b0, uint32_t b1) {
    asm volatile(
        "mma.sync.aligned.m16n8k16.row.col.f32.bf16.bf16.f32 "
        "{%0,%1,%2,%3}, {%4,%5,%6,%7}, {%8,%9}, {%0,%1,%2,%3};"
        : "+f"(d[0]), "+f"(d[1]), "+f"(d[2]), "+f"(d[3])
        : "r"(a[0]), "r"(a[1]), "r"(a[2]), "r"(a[3]), "r"(b0), "r"(b1));
}

__global__ __launch_bounds__(256) void gemm_kernel(float* __restrict__ out) {
    __shared__ __align__(16) __nv_bfloat16 sA[128 * SA_STRIDE];
    __shared__ __align__(16) __nv_bfloat16 sB[128 * SA_STRIDE];
    __shared__ float sXsq[128];
    __shared__ float sWsq[128];

    const int tid  = threadIdx.x;
    const int lane = tid & 31;
    const int warp = tid >> 5;
    const int wm = warp & 3;   // 4 warps in M
    const int wn = warp >> 2;  // 2 warps in N
    const int m0 = blockIdx.y * 128;
    const int n0 = blockIdx.x * 128;

    if (tid < 128) {
        sXsq[tid] = g_xsq[m0 + tid];
        sWsq[tid] = g_wsq[n0 + tid];
    }

    float acc[2][8][4];
#pragma unroll
    for (int mi = 0; mi < 2; mi++)
#pragma unroll
        for (int ni = 0; ni < 8; ni++)
#pragma unroll
            for (int e = 0; e < 4; e++) acc[mi][ni][e] = 0.0f;

    // precompute ldmatrix shared addresses (lane-dependent parts)
    const int a_row = (lane & 15);
    const int a_cg  = (lane >> 4) << 3;
    const int b_r   = lane & 7;
    const int b_sel = lane >> 3;
    const int b_nof = ((b_sel >> 1) << 3) + b_r;
    const int b_kof = (b_sel & 1) << 3;

    for (int kc = 0; kc < DFEAT; kc += 64) {
        __syncthreads();
        // load A tile 128x64 and B tile 128x64 (bf16), 8 bf16 per ld
#pragma unroll
        for (int p = 0; p < 4; p++) {
            int e = p * 2048 + tid * 8;
            int r = e >> 6;
            int c = e & 63;
            *reinterpret_cast<uint4*>(&sA[r * SA_STRIDE + c]) =
                *reinterpret_cast<const uint4*>(&g_xb[(size_t)(m0 + r) * DFEAT + kc + c]);
            *reinterpret_cast<uint4*>(&sB[r * SA_STRIDE + c]) =
                *reinterpret_cast<const uint4*>(&g_wb[(size_t)(n0 + r) * DFEAT + kc + c]);
        }
        __syncthreads();

#pragma unroll
        for (int ks = 0; ks < 64; ks += 16) {
            uint32_t af[2][4];
#pragma unroll
            for (int mi = 0; mi < 2; mi++) {
                int r = wm * 32 + mi * 16 + a_row;
                int c = ks + a_cg;
                uint32_t ad = (uint32_t)__cvta_generic_to_shared(&sA[r * SA_STRIDE + c]);
                ldmatrix_x4(af[mi][0], af[mi][1], af[mi][2], af[mi][3], ad);
            }
            uint32_t bfr[4][4];
#pragma unroll
            for (int j = 0; j < 4; j++) {
                int n = wn * 64 + j * 16 + b_nof;
                int c = ks + b_kof;
                uint32_t bd = (uint32_t)__cvta_generic_to_shared(&sB[n * SA_STRIDE + c]);
                ldmatrix_x4(bfr[j][0], bfr[j][1], bfr[j][2], bfr[j][3], bd);
            }
#pragma unroll
            for (int mi = 0; mi < 2; mi++)
#pragma unroll
                for (int ni = 0; ni < 8; ni++) {
                    int j = ni >> 1, h = (ni & 1) * 2;
                    mma_bf16(acc[mi][ni], af[mi], bfr[j][h], bfr[j][h + 1]);
                }
        }
    }

    // Fused epilogue: q_un = 1/(1+max(dist,0))
    const int qt = lane >> 2;  // row within 8
    const int qr = lane & 3;   // col pair selector
#pragma unroll
    for (int mi = 0; mi < 2; mi++) {
        int lr = wm * 32 + mi * 16 + qt;
        float xs0 = sXsq[lr];
        float xs1 = sXsq[lr + 8];
        int gr0 = (m0 + lr) * KOUT;
        int gr1 = gr0 + 8 * KOUT;
#pragma unroll
        for (int ni = 0; ni < 8; ni++) {
            int nl = wn * 64 + ni * 8 + qr * 2;
            float w0 = sWsq[nl];
            float w1 = sWsq[nl + 1];
            const float* d = acc[mi][ni];
            float q00 = 1.0f / (1.0f + fmaxf(xs0 + w0 - 2.0f * d[0], 0.0f));
            float q01 = 1.0f / (1.0f + fmaxf(xs0 + w1 - 2.0f * d[1], 0.0f));
            float q10 = 1.0f / (1.0f + fmaxf(xs1 + w0 - 2.0f * d[2], 0.0f));
            float q11 = 1.0f / (1.0f + fmaxf(xs1 + w1 - 2.0f * d[3], 0.0f));
            *reinterpret_cast<float2*>(&out[gr0 + n0 + nl]) = make_float2(q00, q01);
            *reinterpret_cast<float2*>(&out[gr1 + n0 + nl]) = make_float2(q10, q11);
        }
    }
}

// ---------------------------------------------------------------------------
// Kernel 3: deterministic row normalization (warp per row, no atomics).
// Reads q back (L2-hot: 32 MB output fits L2), scales, writes.
// ---------------------------------------------------------------------------
__global__ void norm_kernel(float* __restrict__ out) {
    int warp = threadIdx.x >> 5;
    int lane = threadIdx.x & 31;
    int row  = blockIdx.x * 8 + warp;
    float* p = out + (size_t)row * KOUT;

    float4 v[8];
    float s = 0.0f;
#pragma unroll
    for (int i = 0; i < 8; i++) {
        v[i] = *reinterpret_cast<float4*>(&p[i * 128 + lane * 4]);
        s += v[i].x + v[i].y + v[i].z + v[i].w;
    }
#pragma unroll
    for (int off = 16; off >= 1; off >>= 1)
        s += __shfl_xor_sync(0xFFFFFFFFu, s, off);
    float inv = 1.0f / s;
#pragma unroll
    for (int i = 0; i < 8; i++) {
        v[i].x *= inv; v[i].y *= inv; v[i].z *= inv; v[i].w *= inv;
        *reinterpret_cast<float4*>(&p[i * 128 + lane * 4]) = v[i];
    }
}

// ---------------------------------------------------------------------------
extern "C" void kernel_launch(void* const* d_in, const int* in_sizes, int n_in,
                              void* d_out, int out_size) {
    const float* x = (const float*)d_in[0];   // [8192, 512] f32
    const float* w = (const float*)d_in[1];   // [1024, 512] f32
    float* out = (float*)d_out;               // [8192, 1024] f32

    // 9216 rows total, 8 warps per 256-thread block
    prep_kernel<<<(B_ROWS + KOUT) / 8, 256>>>(x, w);
    gemm_kernel<<<dim3(KOUT / 128, B_ROWS / 128), 256>>>(out);
    norm_kernel<<<B_ROWS / 8, 256>>>(out);
}